// round 9
// baseline (speedup 1.0000x reference)
#include <cuda_runtime.h>
#include <cstdint>

// Stacked LSTM (2 layers, D=H=6) + softmax, sm_103a.
// One lane owns TWO batch elements (4 independent LSTM cells per warp-step:
// 2 layers x 2 elems), maximizing in-warp ILP for this latency-bound
// recurrence. Weights in registers (shared across the lane's two elements),
// packed gate pairs (i,f)/(g,o) via fma.rn.f32x2; sigmoid gates pre-halved
// (sigmoid = tanh.approx + FFMA); layers software-pipelined with 1-step skew.

#define FULLMASK 0xFFFFFFFFu
typedef unsigned long long ull;

__device__ __forceinline__ float ex2f(float x) {
    float r; asm("ex2.approx.f32 %0, %1;" : "=f"(r) : "f"(x)); return r;
}
__device__ __forceinline__ float rcpf(float x) {
    float r; asm("rcp.approx.f32 %0, %1;" : "=f"(r) : "f"(x)); return r;
}
__device__ __forceinline__ float htanh(float x) {
    float r; asm("tanh.approx.f32 %0, %1;" : "=f"(r) : "f"(x)); return r;
}
__device__ __forceinline__ ull pack2(float lo, float hi) {
    ull r; asm("mov.b64 %0, {%1, %2};" : "=l"(r) : "f"(lo), "f"(hi)); return r;
}
__device__ __forceinline__ ull dup2(float v) {
    ull r; asm("mov.b64 %0, {%1, %1};" : "=l"(r) : "f"(v)); return r;
}
__device__ __forceinline__ void unpack2(ull v, float& lo, float& hi) {
    asm("mov.b64 {%0, %1}, %2;" : "=f"(lo), "=f"(hi) : "l"(v));
}
__device__ __forceinline__ ull ffma2(ull a, ull b, ull c) {
    ull d; asm("fma.rn.f32x2 %0, %1, %2, %3;" : "=l"(d) : "l"(a), "l"(b), "l"(c)); return d;
}

__device__ __forceinline__ void gates_update(ull p01, ull p23, float& c, float& nh) {
    float a0, a1, a2, a3;
    unpack2(p01, a0, a1);
    unpack2(p23, a2, a3);
    float ig = fmaf(0.5f, htanh(a0), 0.5f);
    float fg = fmaf(0.5f, htanh(a1), 0.5f);
    float gg = htanh(a2);
    float og = fmaf(0.5f, htanh(a3), 0.5f);
    c  = fmaf(fg, c, ig * gg);
    nh = og * htanh(c);
}

__global__ __launch_bounds__(128, 1)
void stacked_lstm_kernel(const float* __restrict__ x,
                         const float* __restrict__ Wih0, const float* __restrict__ Whh0,
                         const float* __restrict__ bih0, const float* __restrict__ bhh0,
                         const float* __restrict__ Wih1, const float* __restrict__ Whh1,
                         const float* __restrict__ bih1, const float* __restrict__ bhh1,
                         float* __restrict__ out,
                         int B, int T) {
    const int lane = threadIdx.x & 31;
    const int warp_global = (blockIdx.x * blockDim.x + threadIdx.x) >> 5;
    const int g = lane / 6;          // group within warp (0..4 active)
    const int j = lane - g * 6;      // hidden unit owned by this lane
    const int base = g * 6;
    const int bA = warp_global * 10 + g;        // element A
    const int bB = warp_global * 10 + 5 + g;    // element B
    const bool validA = (g < 5) && (bA < B);
    const bool validB = (g < 5) && (bB < B);
    const int bcA = (bA < B) ? bA : (B - 1);
    const int bcB = (bB < B) ? bB : (B - 1);

    // ---- packed weights (shared by both elements): pairs (i,f) and (g,o) ----
    ull wi0p01[6], wi0p23[6], wh0p01[6], wh0p23[6];
    ull wi1p01[6], wi1p23[6], wh1p01[6], wh1p23[6];
    ull bz0p01, bz0p23, bz1p01, bz1p23;
    {
        const float s0 = 0.5f, s1 = 0.5f, s2 = 1.0f, s3 = 0.5f;  // i,f,g,o
        int r0 = j, r1 = 6 + j, r2 = 12 + j, r3 = 18 + j;
        bz0p01 = pack2((bih0[r0] + bhh0[r0]) * s0, (bih0[r1] + bhh0[r1]) * s1);
        bz0p23 = pack2((bih0[r2] + bhh0[r2]) * s2, (bih0[r3] + bhh0[r3]) * s3);
        bz1p01 = pack2((bih1[r0] + bhh1[r0]) * s0, (bih1[r1] + bhh1[r1]) * s1);
        bz1p23 = pack2((bih1[r2] + bhh1[r2]) * s2, (bih1[r3] + bhh1[r3]) * s3);
#pragma unroll
        for (int d = 0; d < 6; ++d) {
            wi0p01[d] = pack2(Wih0[r0 * 6 + d] * s0, Wih0[r1 * 6 + d] * s1);
            wi0p23[d] = pack2(Wih0[r2 * 6 + d] * s2, Wih0[r3 * 6 + d] * s3);
            wh0p01[d] = pack2(Whh0[r0 * 6 + d] * s0, Whh0[r1 * 6 + d] * s1);
            wh0p23[d] = pack2(Whh0[r2 * 6 + d] * s2, Whh0[r3 * 6 + d] * s3);
            wi1p01[d] = pack2(Wih1[r0 * 6 + d] * s0, Wih1[r1 * 6 + d] * s1);
            wi1p23[d] = pack2(Wih1[r2 * 6 + d] * s2, Wih1[r3 * 6 + d] * s3);
            wh1p01[d] = pack2(Whh1[r0 * 6 + d] * s0, Whh1[r1 * 6 + d] * s1);
            wh1p23[d] = pack2(Whh1[r2 * 6 + d] * s2, Whh1[r3 * 6 + d] * s3);
        }
    }

    // ---- per-element state ----
    float c0A = 0.0f, c1A = 0.0f, c0B = 0.0f, c1B = 0.0f;
    ull hp0A[6], hp1A[6], hp0B[6], hp1B[6];
#pragma unroll
    for (int k = 0; k < 6; ++k) { hp0A[k] = hp1A[k] = hp0B[k] = hp1B[k] = 0ull; }

    const float2* xpA = reinterpret_cast<const float2*>(x + (size_t)bcA * (size_t)T * 6);
    const float2* xpB = reinterpret_cast<const float2*>(x + (size_t)bcB * (size_t)T * 6);

    // one-step-ahead layer0 x-projections
    ull xa01A, xa23A, xa01B, xa23B;
    {
        float2 u0 = xpA[0], u1 = xpA[1], u2 = xpA[2];
        float2 v0 = xpB[0], v1 = xpB[1], v2 = xpB[2];
        float xiA[6] = {u0.x, u0.y, u1.x, u1.y, u2.x, u2.y};
        float xiB[6] = {v0.x, v0.y, v1.x, v1.y, v2.x, v2.y};
        xa01A = bz0p01; xa23A = bz0p23; xa01B = bz0p01; xa23B = bz0p23;
#pragma unroll
        for (int d = 0; d < 6; ++d) {
            ull xvA = dup2(xiA[d]), xvB = dup2(xiB[d]);
            xa01A = ffma2(wi0p01[d], xvA, xa01A);
            xa23A = ffma2(wi0p23[d], xvA, xa23A);
            xa01B = ffma2(wi0p01[d], xvB, xa01B);
            xa23B = ffma2(wi0p23[d], xvB, xa23B);
        }
        asm volatile("prefetch.global.L2 [%0];" :: "l"(xpA + 3 * 32));
        asm volatile("prefetch.global.L2 [%0];" :: "l"(xpB + 3 * 32));
    }

    float nh0A, nh1A, nh0B, nh1B;

    // ---- t = 0: layer0 only (h is zero; dots reduce to the x-projection) ----
    {
        ull a01A = xa01A, a23A = xa23A, a01B = xa01B, a23B = xa23B;
        // next x-projection (t = 1)
        float2 u0 = xpA[3], u1 = xpA[4], u2 = xpA[5];
        float2 v0 = xpB[3], v1 = xpB[4], v2 = xpB[5];
        float xiA[6] = {u0.x, u0.y, u1.x, u1.y, u2.x, u2.y};
        float xiB[6] = {v0.x, v0.y, v1.x, v1.y, v2.x, v2.y};
        xa01A = bz0p01; xa23A = bz0p23; xa01B = bz0p01; xa23B = bz0p23;
#pragma unroll
        for (int d = 0; d < 6; ++d) {
            ull xvA = dup2(xiA[d]), xvB = dup2(xiB[d]);
            xa01A = ffma2(wi0p01[d], xvA, xa01A);
            xa23A = ffma2(wi0p23[d], xvA, xa23A);
            xa01B = ffma2(wi0p01[d], xvB, xa01B);
            xa23B = ffma2(wi0p23[d], xvB, xa23B);
        }
        gates_update(a01A, a23A, c0A, nh0A);
        gates_update(a01B, a23B, c0B, nh0B);
#pragma unroll
        for (int k = 0; k < 6; ++k) {
            hp0A[k] = dup2(__shfl_sync(FULLMASK, nh0A, base + k));
            hp0B[k] = dup2(__shfl_sync(FULLMASK, nh0B, base + k));
        }
    }

    // ---- main loop: iteration t computes layer0(t) and layer1(t-1), x2 elems ----
    for (int t = 1; t < T; ++t) {
        // layer1 dots @ t-1 (independent of layer0 chain)
        ull b01A = bz1p01, b23A = bz1p23, b01B = bz1p01, b23B = bz1p23;
#pragma unroll
        for (int d = 0; d < 6; ++d) {
            b01A = ffma2(wi1p01[d], hp0A[d], b01A);
            b23A = ffma2(wi1p23[d], hp0A[d], b23A);
            b01B = ffma2(wi1p01[d], hp0B[d], b01B);
            b23B = ffma2(wi1p23[d], hp0B[d], b23B);
        }
#pragma unroll
        for (int d = 0; d < 6; ++d) {
            b01A = ffma2(wh1p01[d], hp1A[d], b01A);
            b23A = ffma2(wh1p23[d], hp1A[d], b23A);
            b01B = ffma2(wh1p01[d], hp1B[d], b01B);
            b23B = ffma2(wh1p23[d], hp1B[d], b23B);
        }

        // layer0 recurrent dots @ t
        ull a01A = xa01A, a23A = xa23A, a01B = xa01B, a23B = xa23B;
#pragma unroll
        for (int d = 0; d < 6; ++d) {
            a01A = ffma2(wh0p01[d], hp0A[d], a01A);
            a23A = ffma2(wh0p23[d], hp0A[d], a23A);
            a01B = ffma2(wh0p01[d], hp0B[d], a01B);
            a23B = ffma2(wh0p23[d], hp0B[d], a23B);
        }

        // next x-projection (t+1) — independent, fills stall cycles
        {
            int tn = (t + 1 < T) ? (t + 1) : t;
            float2 u0 = xpA[3 * tn], u1 = xpA[3 * tn + 1], u2 = xpA[3 * tn + 2];
            float2 v0 = xpB[3 * tn], v1 = xpB[3 * tn + 1], v2 = xpB[3 * tn + 2];
            float xiA[6] = {u0.x, u0.y, u1.x, u1.y, u2.x, u2.y};
            float xiB[6] = {v0.x, v0.y, v1.x, v1.y, v2.x, v2.y};
            xa01A = bz0p01; xa23A = bz0p23; xa01B = bz0p01; xa23B = bz0p23;
#pragma unroll
            for (int d = 0; d < 6; ++d) {
                ull xvA = dup2(xiA[d]), xvB = dup2(xiB[d]);
                xa01A = ffma2(wi0p01[d], xvA, xa01A);
                xa23A = ffma2(wi0p23[d], xvA, xa23A);
                xa01B = ffma2(wi0p01[d], xvB, xa01B);
                xa23B = ffma2(wi0p23[d], xvB, xa23B);
            }
        }
        if (t + 32 < T) {
            asm volatile("prefetch.global.L2 [%0];" :: "l"(xpA + 3 * (t + 32)));
            asm volatile("prefetch.global.L2 [%0];" :: "l"(xpB + 3 * (t + 32)));
        }

        gates_update(a01A, a23A, c0A, nh0A);
        gates_update(b01A, b23A, c1A, nh1A);
        gates_update(a01B, a23B, c0B, nh0B);
        gates_update(b01B, b23B, c1B, nh1B);

#pragma unroll
        for (int k = 0; k < 6; ++k) {
            hp0A[k] = dup2(__shfl_sync(FULLMASK, nh0A, base + k));
            hp1A[k] = dup2(__shfl_sync(FULLMASK, nh1A, base + k));
            hp0B[k] = dup2(__shfl_sync(FULLMASK, nh0B, base + k));
            hp1B[k] = dup2(__shfl_sync(FULLMASK, nh1B, base + k));
        }
    }

    // ---- final skewed layer1 step @ t = T-1 ----
    {
        ull b01A = bz1p01, b23A = bz1p23, b01B = bz1p01, b23B = bz1p23;
#pragma unroll
        for (int d = 0; d < 6; ++d) {
            b01A = ffma2(wi1p01[d], hp0A[d], b01A);
            b23A = ffma2(wi1p23[d], hp0A[d], b23A);
            b01B = ffma2(wi1p01[d], hp0B[d], b01B);
            b23B = ffma2(wi1p23[d], hp0B[d], b23B);
        }
#pragma unroll
        for (int d = 0; d < 6; ++d) {
            b01A = ffma2(wh1p01[d], hp1A[d], b01A);
            b23A = ffma2(wh1p23[d], hp1A[d], b23A);
            b01B = ffma2(wh1p01[d], hp1B[d], b01B);
            b23B = ffma2(wh1p23[d], hp1B[d], b23B);
        }
        gates_update(b01A, b23A, c1A, nh1A);
        gates_update(b01B, b23B, c1B, nh1B);
#pragma unroll
        for (int k = 0; k < 6; ++k) {
            hp1A[k] = dup2(__shfl_sync(FULLMASK, nh1A, base + k));
            hp1B[k] = dup2(__shfl_sync(FULLMASK, nh1B, base + k));
        }
    }

    // ---- softmax over 6 units; lane j writes both elements ----
    {
        float hA[6], hB[6], dummy;
#pragma unroll
        for (int k = 0; k < 6; ++k) { unpack2(hp1A[k], hA[k], dummy); unpack2(hp1B[k], hB[k], dummy); }
        if (validA) {
            float m = hA[0];
#pragma unroll
            for (int k = 1; k < 6; ++k) m = fmaxf(m, hA[k]);
            float s = 0.0f;
#pragma unroll
            for (int k = 0; k < 6; ++k) s += ex2f(1.4426950408889634f * (hA[k] - m));
            float e = ex2f(1.4426950408889634f * (hA[j] - m));
            out[bA * 6 + j] = e * rcpf(s);
        }
        if (validB) {
            float m = hB[0];
#pragma unroll
            for (int k = 1; k < 6; ++k) m = fmaxf(m, hB[k]);
            float s = 0.0f;
#pragma unroll
            for (int k = 0; k < 6; ++k) s += ex2f(1.4426950408889634f * (hB[k] - m));
            float e = ex2f(1.4426950408889634f * (hB[j] - m));
            out[bB * 6 + j] = e * rcpf(s);
        }
    }
}

extern "C" void kernel_launch(void* const* d_in, const int* in_sizes, int n_in,
                              void* d_out, int out_size) {
    const float* x    = (const float*)d_in[0];
    const float* Wih0 = (const float*)d_in[1];
    const float* Whh0 = (const float*)d_in[2];
    const float* bih0 = (const float*)d_in[3];
    const float* bhh0 = (const float*)d_in[4];
    const float* Wih1 = (const float*)d_in[5];
    const float* Whh1 = (const float*)d_in[6];
    const float* bih1 = (const float*)d_in[7];
    const float* bhh1 = (const float*)d_in[8];
    float* out = (float*)d_out;

    int B = out_size / 6;
    int T = (int)((long long)in_sizes[0] / ((long long)B * 6));

    int warps = (B + 9) / 10;         // 10 batch elements per warp (2 per lane-group)
    int blocks = (warps + 3) / 4;     // 4 warps per block
    stacked_lstm_kernel<<<blocks, 128>>>(x, Wih0, Whh0, bih0, bhh0,
                                         Wih1, Whh1, bih1, bhh1, out, B, T);
}

// round 14
// speedup vs baseline: 1.2742x; 1.2742x over previous
#include <cuda_runtime.h>
#include <cstdint>

// Stacked LSTM (2 layers, D=H=6) + softmax, sm_103a.
// Wall time for this serial recurrence = single-warp per-step latency x T, so
// the design minimizes the per-step instruction schedule of one warp:
//  - The layer-0 input projection Wih0*x(t)+b has NO recurrent dependence; a
//    separate bandwidth-bound kernel precomputes it for all (b,t) into a
//    __device__ scratch as float4{i,f,g,o} (pre-scaled, bias folded). The
//    recurrent loop then starts each step from ONE LDG.128 whose destination
//    registers are already the two packed FFMA2 accumulators.
//  - Gate pairs (i,f)/(g,o) in packed fma.rn.f32x2; sigmoid gates pre-halved
//    (sigmoid = tanh.approx + FFMA); layers software-pipelined (1-step skew);
//    h broadcast as packed {h,h} 64-bit shuffles.
// NOTE: one float4 == one ulonglong2 == 16 bytes, so the per-step stride of
// 6 float4 (one per hidden unit) is SIX ulonglong2 (R11 bug: used 3).

#define FULLMASK 0xFFFFFFFFu
typedef unsigned long long ull;

// 2048 x 2048 x 6 units -> 402.7 MB scratch (problem shape is fixed).
#define XG_CAP (2048u * 2048u * 6u)
__device__ float4 g_xg[XG_CAP];

__device__ __forceinline__ float ex2f(float x) {
    float r; asm("ex2.approx.f32 %0, %1;" : "=f"(r) : "f"(x)); return r;
}
__device__ __forceinline__ float rcpf(float x) {
    float r; asm("rcp.approx.f32 %0, %1;" : "=f"(r) : "f"(x)); return r;
}
__device__ __forceinline__ float htanh(float x) {
    float r; asm("tanh.approx.f32 %0, %1;" : "=f"(r) : "f"(x)); return r;
}
__device__ __forceinline__ ull pack2(float lo, float hi) {
    ull r; asm("mov.b64 %0, {%1, %2};" : "=l"(r) : "f"(lo), "f"(hi)); return r;
}
__device__ __forceinline__ ull dup2(float v) {
    ull r; asm("mov.b64 %0, {%1, %1};" : "=l"(r) : "f"(v)); return r;
}
__device__ __forceinline__ void unpack2(ull v, float& lo, float& hi) {
    asm("mov.b64 {%0, %1}, %2;" : "=f"(lo), "=f"(hi) : "l"(v));
}
__device__ __forceinline__ ull ffma2(ull a, ull b, ull c) {
    ull d; asm("fma.rn.f32x2 %0, %1, %2, %3;" : "=l"(d) : "l"(a), "l"(b), "l"(c)); return d;
}

__device__ __forceinline__ void gates_update(ull p01, ull p23, float& c, float& nh) {
    float a0, a1, a2, a3;
    unpack2(p01, a0, a1);
    unpack2(p23, a2, a3);
    float ig = fmaf(0.5f, htanh(a0), 0.5f);
    float fg = fmaf(0.5f, htanh(a1), 0.5f);
    float gg = htanh(a2);
    float og = fmaf(0.5f, htanh(a3), 0.5f);
    c  = fmaf(fg, c, ig * gg);
    nh = og * htanh(c);
}

// ---- kernel 1: xg[b][t][j] = {0.5*(Wih0_i.x+b_i), 0.5*(...f), (...g), 0.5*(...o)} ----
__global__ void xg_precompute_kernel(const float* __restrict__ x,
                                     const float* __restrict__ Wih0,
                                     const float* __restrict__ bih0,
                                     const float* __restrict__ bhh0,
                                     int total /* B*T*6 */) {
    int idx = blockIdx.x * blockDim.x + threadIdx.x;
    if (idx >= total) return;
    int j  = idx % 6;
    int bt = idx / 6;
    const float* xv = x + (size_t)bt * 6;
    float xr[6];
#pragma unroll
    for (int d = 0; d < 6; ++d) xr[d] = xv[d];
    float acc[4];
#pragma unroll
    for (int q = 0; q < 4; ++q) {
        int r = q * 6 + j;
        float a = bih0[r] + bhh0[r];
#pragma unroll
        for (int d = 0; d < 6; ++d) a = fmaf(Wih0[r * 6 + d], xr[d], a);
        acc[q] = a;
    }
    g_xg[idx] = make_float4(0.5f * acc[0], 0.5f * acc[1], acc[2], 0.5f * acc[3]);
}

// ---- kernel 2: the recurrence ----
__global__ __launch_bounds__(128, 1)
void stacked_lstm_kernel(const float* __restrict__ Whh0,
                         const float* __restrict__ Wih1, const float* __restrict__ Whh1,
                         const float* __restrict__ bih1, const float* __restrict__ bhh1,
                         float* __restrict__ out,
                         int B, int T) {
    const int lane = threadIdx.x & 31;
    const int warp_global = (blockIdx.x * blockDim.x + threadIdx.x) >> 5;
    const int g = lane / 6;          // group within warp (0..4 active)
    const int j = lane - g * 6;      // hidden unit owned by this lane
    const int base = g * 6;
    const int b = warp_global * 5 + g;
    const bool valid = (g < 5) && (b < B);
    const int bc = (b < B) ? b : (B - 1);

    // ---- packed weights: pairs (i,f) and (g,o); i,f,o rows pre-halved ----
    ull wh0p01[6], wh0p23[6];
    ull wi1p01[6], wi1p23[6], wh1p01[6], wh1p23[6];
    ull bz1p01, bz1p23;
    {
        const float s0 = 0.5f, s1 = 0.5f, s2 = 1.0f, s3 = 0.5f;  // gate order i,f,g,o
        int r0 = j, r1 = 6 + j, r2 = 12 + j, r3 = 18 + j;
        bz1p01 = pack2((bih1[r0] + bhh1[r0]) * s0, (bih1[r1] + bhh1[r1]) * s1);
        bz1p23 = pack2((bih1[r2] + bhh1[r2]) * s2, (bih1[r3] + bhh1[r3]) * s3);
#pragma unroll
        for (int d = 0; d < 6; ++d) {
            wh0p01[d] = pack2(Whh0[r0 * 6 + d] * s0, Whh0[r1 * 6 + d] * s1);
            wh0p23[d] = pack2(Whh0[r2 * 6 + d] * s2, Whh0[r3 * 6 + d] * s3);
            wi1p01[d] = pack2(Wih1[r0 * 6 + d] * s0, Wih1[r1 * 6 + d] * s1);
            wi1p23[d] = pack2(Wih1[r2 * 6 + d] * s2, Wih1[r3 * 6 + d] * s3);
            wh1p01[d] = pack2(Whh1[r0 * 6 + d] * s0, Whh1[r1 * 6 + d] * s1);
            wh1p23[d] = pack2(Whh1[r2 * 6 + d] * s2, Whh1[r3 * 6 + d] * s3);
        }
    }

    // ---- state ----
    float c0 = 0.0f, c1 = 0.0f;
    ull hp0[6], hp1[6];              // packed {h,h} broadcasts
#pragma unroll
    for (int k = 0; k < 6; ++k) { hp0[k] = 0ull; hp1[k] = 0ull; }

    // xg stream for this lane: one ulonglong2 per step ({i,f},{g,o}).
    // Per-step stride = 6 float4 = 6 ulonglong2 (16 B each).
    const ulonglong2* xgp = reinterpret_cast<const ulonglong2*>(
        g_xg + ((size_t)bc * (size_t)T) * 6 + j);
    ulonglong2 xg_cur = xgp[0];
    ulonglong2 xg_nxt = (T > 1) ? xgp[6] : xg_cur;

    float nh0, nh1;

    // ---- t = 0: layer0 only (h0 = 0 -> preact = xg directly) ----
    {
        asm volatile("prefetch.global.L2 [%0];" :: "l"(xgp + 6 * 32));
        gates_update(xg_cur.x, xg_cur.y, c0, nh0);
        ull nhp = dup2(nh0);
#pragma unroll
        for (int k = 0; k < 6; ++k) hp0[k] = __shfl_sync(FULLMASK, nhp, base + k);
        xg_cur = xg_nxt;
        xg_nxt = (T > 2) ? xgp[2 * 6] : xg_cur;
    }

    // ---- main loop: iteration t computes layer0(t) and layer1(t-1) ----
    for (int t = 1; t < T; ++t) {
        // layer1 dots @ t-1 (uses hp0 = h0(t-1), hp1 = h1(t-2))
        ull b01 = bz1p01, b23 = bz1p23;
#pragma unroll
        for (int d = 0; d < 6; ++d) {
            b01 = ffma2(wi1p01[d], hp0[d], b01);
            b23 = ffma2(wi1p23[d], hp0[d], b23);
        }
#pragma unroll
        for (int d = 0; d < 6; ++d) {
            b01 = ffma2(wh1p01[d], hp1[d], b01);
            b23 = ffma2(wh1p23[d], hp1[d], b23);
        }

        // layer0 recurrent dots @ t (accumulator initialized from precomputed xg)
        ull a01 = xg_cur.x, a23 = xg_cur.y;
#pragma unroll
        for (int d = 0; d < 6; ++d) {
            a01 = ffma2(wh0p01[d], hp0[d], a01);
            a23 = ffma2(wh0p23[d], hp0[d], a23);
        }

        // advance the 2-step-ahead xg register pipeline
        xg_cur = xg_nxt;
        {
            int tn = (t + 2 < T) ? (t + 2) : (T - 1);
            xg_nxt = xgp[(size_t)tn * 6];
        }
        if (t + 32 < T)
            asm volatile("prefetch.global.L2 [%0];" :: "l"(xgp + (size_t)(t + 32) * 6));

        gates_update(a01, a23, c0, nh0);   // layer0 @ t
        gates_update(b01, b23, c1, nh1);   // layer1 @ t-1

        ull nhp0 = dup2(nh0), nhp1 = dup2(nh1);
#pragma unroll
        for (int k = 0; k < 6; ++k) {
            hp0[k] = __shfl_sync(FULLMASK, nhp0, base + k);
            hp1[k] = __shfl_sync(FULLMASK, nhp1, base + k);
        }
    }

    // ---- final skewed layer1 step @ t = T-1 ----
    {
        ull b01 = bz1p01, b23 = bz1p23;
#pragma unroll
        for (int d = 0; d < 6; ++d) {
            b01 = ffma2(wi1p01[d], hp0[d], b01);
            b23 = ffma2(wi1p23[d], hp0[d], b23);
        }
#pragma unroll
        for (int d = 0; d < 6; ++d) {
            b01 = ffma2(wh1p01[d], hp1[d], b01);
            b23 = ffma2(wh1p23[d], hp1[d], b23);
        }
        gates_update(b01, b23, c1, nh1);
        ull nhp1 = dup2(nh1);
#pragma unroll
        for (int k = 0; k < 6; ++k) hp1[k] = __shfl_sync(FULLMASK, nhp1, base + k);
    }

    // ---- softmax over 6 units; lane j writes out[b, j] ----
    if (valid) {
        float h1f[6], dummy;
#pragma unroll
        for (int k = 0; k < 6; ++k) unpack2(hp1[k], h1f[k], dummy);
        float m = h1f[0];
#pragma unroll
        for (int k = 1; k < 6; ++k) m = fmaxf(m, h1f[k]);
        float s = 0.0f;
#pragma unroll
        for (int k = 0; k < 6; ++k) s += ex2f(1.4426950408889634f * (h1f[k] - m));
        float e = ex2f(1.4426950408889634f * (h1f[j] - m));
        out[b * 6 + j] = e * rcpf(s);
    }
}

extern "C" void kernel_launch(void* const* d_in, const int* in_sizes, int n_in,
                              void* d_out, int out_size) {
    const float* x    = (const float*)d_in[0];
    const float* Wih0 = (const float*)d_in[1];
    const float* Whh0 = (const float*)d_in[2];
    const float* bih0 = (const float*)d_in[3];
    const float* bhh0 = (const float*)d_in[4];
    const float* Wih1 = (const float*)d_in[5];
    const float* Whh1 = (const float*)d_in[6];
    const float* bih1 = (const float*)d_in[7];
    const float* bhh1 = (const float*)d_in[8];
    float* out = (float*)d_out;

    int B = out_size / 6;
    int T = (int)((long long)in_sizes[0] / ((long long)B * 6));

    // kernel 1: input projections for all (b, t)
    int total = B * T * 6;
    xg_precompute_kernel<<<(total + 255) / 256, 256>>>(x, Wih0, bih0, bhh0, total);

    // kernel 2: the recurrence (same stream -> ordered)
    int warps = (B + 4) / 5;
    int blocks = (warps + 3) / 4;
    stacked_lstm_kernel<<<blocks, 128>>>(Whh0, Wih1, Whh1, bih1, bhh1, out, B, T);
}

// round 15
// speedup vs baseline: 1.7592x; 1.3806x over previous
#include <cuda_runtime.h>
#include <cstdint>

// Stacked LSTM (2 layers, D=H=6) + softmax, sm_103a.
// Wall time = single-warp per-step latency x T. The dominant per-step term in
// the champion kernel was per-lane FMA-pipe occupancy (48 FFMA2 x rt4 = 192cyc).
// This version SPLITS each dot product across a lane PAIR: unit j is owned by
// lanes (2j, 2j+1); p=0 handles input dims {0,1,2}, p=1 handles {4,5,3} (slot-
// permuted so x loads map directly). Partial sums combine with one 64-bit
// shfl_xor + add.f32x2 per packed acc. Per-lane FMA work halves (24 FFMA2) and
// h-gather halves (each lane gathers only its 3 dims -> 6 SHFL/step).
// 12 lanes per element, 2 elements per warp (lanes 0-11 and 16-27).
// Gate pairs (i,f)/(g,o) packed via fma.rn.f32x2; sigmoid via tanh.approx with
// pre-halved rows; layers software-pipelined with 1-step skew; biases carry an
// extra 0.5 so the pair-combine sums to the full bias.

#define FULLMASK 0xFFFFFFFFu
typedef unsigned long long ull;

__device__ __forceinline__ float ex2f(float x) {
    float r; asm("ex2.approx.f32 %0, %1;" : "=f"(r) : "f"(x)); return r;
}
__device__ __forceinline__ float rcpf(float x) {
    float r; asm("rcp.approx.f32 %0, %1;" : "=f"(r) : "f"(x)); return r;
}
__device__ __forceinline__ float htanh(float x) {
    float r; asm("tanh.approx.f32 %0, %1;" : "=f"(r) : "f"(x)); return r;
}
__device__ __forceinline__ ull pack2(float lo, float hi) {
    ull r; asm("mov.b64 %0, {%1, %2};" : "=l"(r) : "f"(lo), "f"(hi)); return r;
}
__device__ __forceinline__ ull dup2(float v) {
    ull r; asm("mov.b64 %0, {%1, %1};" : "=l"(r) : "f"(v)); return r;
}
__device__ __forceinline__ void unpack2(ull v, float& lo, float& hi) {
    asm("mov.b64 {%0, %1}, %2;" : "=f"(lo), "=f"(hi) : "l"(v));
}
__device__ __forceinline__ ull ffma2(ull a, ull b, ull c) {
    ull d; asm("fma.rn.f32x2 %0, %1, %2, %3;" : "=l"(d) : "l"(a), "l"(b), "l"(c)); return d;
}
__device__ __forceinline__ ull addx2(ull a, ull b) {
    ull d; asm("add.rn.f32x2 %0, %1, %2;" : "=l"(d) : "l"(a), "l"(b)); return d;
}
// combine partial packed accumulator across the lane pair (xor 1)
__device__ __forceinline__ ull pair_combine(ull v) {
    return addx2(v, __shfl_xor_sync(FULLMASK, v, 1));
}

__device__ __forceinline__ void gates_update(ull p01, ull p23, float& c, float& nh) {
    float a0, a1, a2, a3;
    unpack2(p01, a0, a1);
    unpack2(p23, a2, a3);
    float ig = fmaf(0.5f, htanh(a0), 0.5f);
    float fg = fmaf(0.5f, htanh(a1), 0.5f);
    float gg = htanh(a2);
    float og = fmaf(0.5f, htanh(a3), 0.5f);
    c  = fmaf(fg, c, ig * gg);
    nh = og * htanh(c);
}

__global__ __launch_bounds__(128, 1)
void stacked_lstm_kernel(const float* __restrict__ x,
                         const float* __restrict__ Wih0, const float* __restrict__ Whh0,
                         const float* __restrict__ bih0, const float* __restrict__ bhh0,
                         const float* __restrict__ Wih1, const float* __restrict__ Whh1,
                         const float* __restrict__ bih1, const float* __restrict__ bhh1,
                         float* __restrict__ out,
                         int B, int T) {
    const int lane = threadIdx.x & 31;
    const int warp_global = (blockIdx.x * blockDim.x + threadIdx.x) >> 5;
    const int half = (lane >> 4) & 1;       // element within warp
    const int el   = lane & 15;             // 0..15; 12..15 idle
    const int j    = el >> 1;               // unit (0..7; >=6 invalid)
    const int p    = el & 1;                // which half of input dims
    const bool lact = (el < 12);
    const int gbase = lane & 0x10;          // element base lane
    const int b  = warp_global * 2 + half;
    const int bc = (b < B) ? b : (B - 1);
    const int jc = (j < 6) ? j : 5;

    // slot -> actual input dim (permuted for p=1 so x loads need no selects)
    int dims[3];
    if (p) { dims[0] = 4; dims[1] = 5; dims[2] = 3; }
    else   { dims[0] = 0; dims[1] = 1; dims[2] = 2; }

    // ---- packed weights (this lane's 3 dims only); i,f,o pre-halved ----
    ull wi0p01[3], wi0p23[3], wh0p01[3], wh0p23[3];
    ull wi1p01[3], wi1p23[3], wh1p01[3], wh1p23[3];
    ull bz0p01, bz0p23, bz1p01, bz1p23;   // biases carry extra 0.5 (pair split)
    {
        const float s0 = 0.5f, s1 = 0.5f, s2 = 1.0f, s3 = 0.5f;  // gates i,f,g,o
        int r0 = jc, r1 = 6 + jc, r2 = 12 + jc, r3 = 18 + jc;
        bz0p01 = pack2((bih0[r0] + bhh0[r0]) * (s0 * 0.5f), (bih0[r1] + bhh0[r1]) * (s1 * 0.5f));
        bz0p23 = pack2((bih0[r2] + bhh0[r2]) * (s2 * 0.5f), (bih0[r3] + bhh0[r3]) * (s3 * 0.5f));
        bz1p01 = pack2((bih1[r0] + bhh1[r0]) * (s0 * 0.5f), (bih1[r1] + bhh1[r1]) * (s1 * 0.5f));
        bz1p23 = pack2((bih1[r2] + bhh1[r2]) * (s2 * 0.5f), (bih1[r3] + bhh1[r3]) * (s3 * 0.5f));
#pragma unroll
        for (int s = 0; s < 3; ++s) {
            int d = dims[s];
            wi0p01[s] = pack2(Wih0[r0 * 6 + d] * s0, Wih0[r1 * 6 + d] * s1);
            wi0p23[s] = pack2(Wih0[r2 * 6 + d] * s2, Wih0[r3 * 6 + d] * s3);
            wh0p01[s] = pack2(Whh0[r0 * 6 + d] * s0, Whh0[r1 * 6 + d] * s1);
            wh0p23[s] = pack2(Whh0[r2 * 6 + d] * s2, Whh0[r3 * 6 + d] * s3);
            wi1p01[s] = pack2(Wih1[r0 * 6 + d] * s0, Wih1[r1 * 6 + d] * s1);
            wi1p23[s] = pack2(Wih1[r2 * 6 + d] * s2, Wih1[r3 * 6 + d] * s3);
            wh1p01[s] = pack2(Whh1[r0 * 6 + d] * s0, Whh1[r1 * 6 + d] * s1);
            wh1p23[s] = pack2(Whh1[r2 * 6 + d] * s2, Whh1[r3 * 6 + d] * s3);
        }
    }

    // gather source lanes for this lane's 3 h-slots (unit dims[s] lives on
    // lanes gbase+2*dims[s] and +1; both lanes of a pair hold identical h)
    int hsrc[3];
#pragma unroll
    for (int s = 0; s < 3; ++s) hsrc[s] = gbase + (dims[s] << 1) + p;

    // ---- state ----
    float c0 = 0.0f, c1 = 0.0f;
    ull hp0[3], hp1[3];
#pragma unroll
    for (int s = 0; s < 3; ++s) { hp0[s] = 0ull; hp1[s] = 0ull; }

    // x addressing: p=0 reads {x0,x1}(f2)+x2 ; p=1 reads {x4,x5}(f2)+x3
    const float* xrow = x + (size_t)bc * (size_t)T * 6;
    const float* x2p  = xrow + (p ? 4 : 0);   // float2 part (8B aligned)
    const float* x1p  = xrow + (p ? 3 : 2);   // scalar part

    // one-step-ahead layer0 x-projection (half-dot, bias pre-split)
    ull xa01, xa23;
    {
        float2 v2 = *reinterpret_cast<const float2*>(x2p);
        float  v1 = *x1p;
        float xs[3] = {v2.x, v2.y, v1};
        xa01 = bz0p01; xa23 = bz0p23;
#pragma unroll
        for (int s = 0; s < 3; ++s) {
            ull xv = dup2(xs[s]);
            xa01 = ffma2(wi0p01[s], xv, xa01);
            xa23 = ffma2(wi0p23[s], xv, xa23);
        }
        asm volatile("prefetch.global.L2 [%0];" :: "l"(x2p + 6 * 32));
    }

    float nh0 = 0.0f, nh1 = 0.0f;

    // ---- t = 0: layer0 only (h0 = 0) ----
    {
        ull a01 = pair_combine(xa01);
        ull a23 = pair_combine(xa23);
        // next x-projection (t = 1)
        {
            float2 v2 = *reinterpret_cast<const float2*>(x2p + 6);
            float  v1 = x1p[6];
            float xs[3] = {v2.x, v2.y, v1};
            xa01 = bz0p01; xa23 = bz0p23;
#pragma unroll
            for (int s = 0; s < 3; ++s) {
                ull xv = dup2(xs[s]);
                xa01 = ffma2(wi0p01[s], xv, xa01);
                xa23 = ffma2(wi0p23[s], xv, xa23);
            }
        }
        gates_update(a01, a23, c0, nh0);
#pragma unroll
        for (int s = 0; s < 3; ++s)
            hp0[s] = dup2(__shfl_sync(FULLMASK, nh0, hsrc[s]));
    }

    // ---- main loop: iteration t computes layer0(t) and layer1(t-1) ----
    for (int t = 1; t < T; ++t) {
        // layer1 half-dots @ t-1 (old hp0, hp1) — independent of L0 chain
        ull b01 = bz1p01, b23 = bz1p23;
#pragma unroll
        for (int s = 0; s < 3; ++s) {
            b01 = ffma2(wi1p01[s], hp0[s], b01);
            b23 = ffma2(wi1p23[s], hp0[s], b23);
        }
#pragma unroll
        for (int s = 0; s < 3; ++s) {
            b01 = ffma2(wh1p01[s], hp1[s], b01);
            b23 = ffma2(wh1p23[s], hp1[s], b23);
        }

        // layer0 half-dots @ t
        ull a01 = xa01, a23 = xa23;
#pragma unroll
        for (int s = 0; s < 3; ++s) {
            a01 = ffma2(wh0p01[s], hp0[s], a01);
            a23 = ffma2(wh0p23[s], hp0[s], a23);
        }

        // combine partial sums across the lane pair
        a01 = pair_combine(a01);
        a23 = pair_combine(a23);
        b01 = pair_combine(b01);
        b23 = pair_combine(b23);

        // next x-projection (t+1) — fill work
        {
            int tn = (t + 1 < T) ? (t + 1) : t;
            float2 v2 = *reinterpret_cast<const float2*>(x2p + 6 * tn);
            float  v1 = x1p[6 * tn];
            float xs[3] = {v2.x, v2.y, v1};
            xa01 = bz0p01; xa23 = bz0p23;
#pragma unroll
            for (int s = 0; s < 3; ++s) {
                ull xv = dup2(xs[s]);
                xa01 = ffma2(wi0p01[s], xv, xa01);
                xa23 = ffma2(wi0p23[s], xv, xa23);
            }
        }
        if (t + 32 < T)
            asm volatile("prefetch.global.L2 [%0];" :: "l"(x2p + 6 * (t + 32)));

        gates_update(a01, a23, c0, nh0);   // layer0 @ t
        gates_update(b01, b23, c1, nh1);   // layer1 @ t-1

        // gather only this lane's 3 dims of each h
#pragma unroll
        for (int s = 0; s < 3; ++s) {
            hp0[s] = dup2(__shfl_sync(FULLMASK, nh0, hsrc[s]));
            hp1[s] = dup2(__shfl_sync(FULLMASK, nh1, hsrc[s]));
        }
    }

    // ---- final skewed layer1 step @ t = T-1 ----
    {
        ull b01 = bz1p01, b23 = bz1p23;
#pragma unroll
        for (int s = 0; s < 3; ++s) {
            b01 = ffma2(wi1p01[s], hp0[s], b01);
            b23 = ffma2(wi1p23[s], hp0[s], b23);
        }
#pragma unroll
        for (int s = 0; s < 3; ++s) {
            b01 = ffma2(wh1p01[s], hp1[s], b01);
            b23 = ffma2(wh1p23[s], hp1[s], b23);
        }
        b01 = pair_combine(b01);
        b23 = pair_combine(b23);
        gates_update(b01, b23, c1, nh1);
    }

    // ---- softmax over 6 units; full gather of h1, lane (j, p=0) writes ----
    {
        float h1f[6];
#pragma unroll
        for (int k = 0; k < 6; ++k)
            h1f[k] = __shfl_sync(FULLMASK, nh1, gbase + (k << 1) + p);
        if (lact && p == 0 && b < B) {
            float m = h1f[0];
#pragma unroll
            for (int k = 1; k < 6; ++k) m = fmaxf(m, h1f[k]);
            float s = 0.0f;
#pragma unroll
            for (int k = 0; k < 6; ++k) s += ex2f(1.4426950408889634f * (h1f[k] - m));
            float e = ex2f(1.4426950408889634f * (h1f[j] - m));
            out[b * 6 + j] = e * rcpf(s);
        }
    }
}

extern "C" void kernel_launch(void* const* d_in, const int* in_sizes, int n_in,
                              void* d_out, int out_size) {
    const float* x    = (const float*)d_in[0];
    const float* Wih0 = (const float*)d_in[1];
    const float* Whh0 = (const float*)d_in[2];
    const float* bih0 = (const float*)d_in[3];
    const float* bhh0 = (const float*)d_in[4];
    const float* Wih1 = (const float*)d_in[5];
    const float* Whh1 = (const float*)d_in[6];
    const float* bih1 = (const float*)d_in[7];
    const float* bhh1 = (const float*)d_in[8];
    float* out = (float*)d_out;

    int B = out_size / 6;
    int T = (int)((long long)in_sizes[0] / ((long long)B * 6));

    int warps = (B + 1) / 2;          // 2 batch elements per warp (12 lanes each)
    int blocks = (warps + 3) / 4;     // 4 warps per block
    stacked_lstm_kernel<<<blocks, 128>>>(x, Wih0, Whh0, bih0, bhh0,
                                         Wih1, Whh1, bih1, bhh1, out, B, T);
}